// round 6
// baseline (speedup 1.0000x reference)
#include <cuda_runtime.h>
#include <cstdint>

// Problem constants
#define S_LEN   2048
#define HDIM    64
#define IDIM    32
#define ODIM    32
#define NCHAIN  256                         // B*P
#define OBS_N   (NCHAIN * S_LEN * ODIM)     // 16,777,216
#define HID_N   (NCHAIN * S_LEN * HDIM)     // 33,554,432
#define CHUNK   16
#define NCHUNK  (S_LEN / CHUNK)             // 128

typedef unsigned long long ull;

// ---------------------------------------------------------------------------
// Packed f32x2 helpers
// ---------------------------------------------------------------------------
__device__ __forceinline__ ull f2ull(float lo, float hi) {
    ull r;
    asm("mov.b64 %0, {%1,%2};" : "=l"(r) : "f"(lo), "f"(hi));
    return r;
}
__device__ __forceinline__ void ull2f(ull u, float& lo, float& hi) {
    asm("mov.b64 {%0,%1}, %2;" : "=f"(lo), "=f"(hi) : "l"(u));
}
__device__ __forceinline__ ull fma2(ull a, ull b, ull c) {
    ull d;
    asm("fma.rn.f32x2 %0, %1, %2, %3;" : "=l"(d) : "l"(a), "l"(b), "l"(c));
    return d;
}
__device__ __forceinline__ ull add2(ull a, ull b) {
    ull d;
    asm("add.rn.f32x2 %0, %1, %2;" : "=l"(d) : "l"(a), "l"(b));
    return d;
}

// tanh(x) = 1 - 2/(e^{2x}+1)
__device__ __forceinline__ float tanh_fast(float x) {
    float e;
    asm("ex2.approx.f32 %0, %1;" : "=f"(e) : "f"(x * 2.8853900817779268f));
    float d = e + 1.0f;
    float r;
    asm("rcp.approx.f32 %0, %1;" : "=f"(r) : "f"(d));
    return fmaf(-2.0f, r, 1.0f);
}

__device__ __forceinline__ uint32_t smem_u32(const void* p) {
    return (uint32_t)__cvta_generic_to_shared(p);
}
__device__ __forceinline__ void cp_async16(uint32_t dst, const void* src) {
    asm volatile("cp.async.ca.shared.global [%0], [%1], 16;\n" :: "r"(dst), "l"(src));
}
__device__ __forceinline__ void cp_commit() {
    asm volatile("cp.async.commit_group;\n" ::: "memory");
}
__device__ __forceinline__ void cp_wait_all() {
    asm volatile("cp.async.wait_group 0;\n" ::: "memory");
}
__device__ __forceinline__ void named_bar(int id) {   // 64-thread named barrier
    asm volatile("bar.sync %0, 64;" :: "r"(id) : "memory");
}

// ---------------------------------------------------------------------------
// Fully fused kernel. 2 chains per 256-thread block (8 warps), grid = 128
// -> exactly one block per SM (no SMSP co-residency jitter).
// Per chain ch (0/1):
//   rec warps  (wid = 2*ch, 2*ch+1): each owns 32 h-outputs (1 per lane).
//       Per step: 16 broadcast LDS.128 (prev h row) + 32 FFMA2 + add2 tree +
//       tanh + STS.32 + named bar.sync(1+ch, 64).  No global memory.
//   pre warp   (wid = 4+ch): cp.async x double-buffer + pre-projection.
//   fc  warp   (wid = 6+ch): hidden STG + fc matvec + obs STG.
// Phase pipeline (16 steps per phase), one __syncthreads per phase:
//   phase p: pre computes chunk p | rec runs chunk p-1 | fc drains chunk p-2.
// ---------------------------------------------------------------------------
__global__ void __launch_bounds__(256, 1) fused_rnn_kernel(
    const float* __restrict__ x,
    const float* __restrict__ W_ih,
    const float* __restrict__ b_ih,
    const float* __restrict__ W_hh,
    const float* __restrict__ b_hh,
    const float* __restrict__ W_fc,
    const float* __restrict__ b_fc,
    float* __restrict__ obs,
    float* __restrict__ hid,
    float* __restrict__ h_last)
{
    const int lane = threadIdx.x & 31;
    const int wid  = threadIdx.x >> 5;       // 0..7

    __shared__ float4 xbuf [2][2][CHUNK * 8];     // [chain][buf] 2KB x-chunks
    __shared__ float  psm  [2][2][CHUNK][HDIM];   // pre (bias folded)
    __shared__ float  hbufs[2][2][CHUNK][HDIM];   // hidden rows
    __shared__ float4 zrow [16];                  // h_{-1} = 0

    // ---- role decode ----
    // rec:  wid 0..3  -> chain = wid>>1, sub = wid&1 (output half)
    // pre:  wid 4..5  -> chain = wid-4
    // fc :  wid 6..7  -> chain = wid-6
    const bool is_rec = (wid < 4);
    const bool is_pre = (wid == 4 || wid == 5);
    const int  ch     = is_rec ? (wid >> 1) : (is_pre ? wid - 4 : wid - 6);
    const int  chain  = blockIdx.x * 2 + ch;

    const float* xg = x   + (size_t)chain * (S_LEN * IDIM);
    float*       hg = hid + (size_t)chain * (S_LEN * HDIM);
    float*       og = obs + (size_t)chain * (S_LEN * ODIM);

    ull wreg[32];                              // role-dependent weights
    float biasA = 0.f, biasB = 0.f, bfc = 0.f;
    int out = 0;

    if (is_rec) {
        const int sub = wid & 1;
        out = sub * 32 + lane;                 // owned h output
#pragma unroll
        for (int i = 0; i < 16; i++) {
            float4 v = __ldg((const float4*)(W_hh + out * HDIM) + i);
            wreg[2 * i]     = f2ull(v.x, v.y);
            wreg[2 * i + 1] = f2ull(v.z, v.w);
        }
        if (wid == 0 && lane < 16) zrow[lane] = make_float4(0.f, 0.f, 0.f, 0.f);
    } else if (is_pre) {
        // W_ih rows 2*lane, 2*lane+1 packed into wreg[0..15], wreg[16..31]
#pragma unroll
        for (int i = 0; i < 8; i++) {
            float4 va = __ldg((const float4*)(W_ih + (2 * lane) * IDIM) + i);
            float4 vb = __ldg((const float4*)(W_ih + (2 * lane + 1) * IDIM) + i);
            wreg[2 * i]          = f2ull(va.x, va.y);
            wreg[2 * i + 1]      = f2ull(va.z, va.w);
            wreg[16 + 2 * i]     = f2ull(vb.x, vb.y);
            wreg[16 + 2 * i + 1] = f2ull(vb.z, vb.w);
        }
        biasA = __ldg(b_ih + 2 * lane)     + __ldg(b_hh + 2 * lane);
        biasB = __ldg(b_ih + 2 * lane + 1) + __ldg(b_hh + 2 * lane + 1);
        // Prologue: stream x chunk 0 for this chain
        const float4* src = (const float4*)xg;
        uint32_t dst = smem_u32(&xbuf[ch][0][0]);
#pragma unroll
        for (int j = 0; j < 4; j++)
            cp_async16(dst + (uint32_t)(lane + 32 * j) * 16, src + lane + 32 * j);
        cp_commit();
    } else {
        // fc warp: W_fc row `lane`
#pragma unroll
        for (int i = 0; i < 16; i++) {
            float4 v = __ldg((const float4*)(W_fc + lane * HDIM) + i);
            wreg[2 * i]     = f2ull(v.x, v.y);
            wreg[2 * i + 1] = f2ull(v.z, v.w);
        }
        bfc = __ldg(b_fc + lane);
    }
    __syncthreads();

    float hv = 0.f;                            // rec: last h[out]

    for (int p = 0; p <= NCHUNK + 1; p++) {
        if (is_rec) {
            if (p >= 1 && p <= NCHUNK) {
                const int c = p - 1;
                const int b = c & 1;
                const float4* prow = (c == 0) ? zrow
                                              : (const float4*)hbufs[ch][b ^ 1][CHUNK - 1];
                const float* pcol = &psm[ch][b][0][out];
#pragma unroll 2
                for (int k = 0; k < CHUNK; k++) {
                    const float pre = pcol[k * HDIM];
                    ull a0 = 0, a1 = 0, a2 = 0, a3 = 0;
#pragma unroll
                    for (int i = 0; i < 16; i += 4) {
                        float4 u0 = prow[i],     u1 = prow[i + 1];
                        float4 u2 = prow[i + 2], u3 = prow[i + 3];
                        a0 = fma2(f2ull(u0.x, u0.y), wreg[2 * i],     a0);
                        a1 = fma2(f2ull(u0.z, u0.w), wreg[2 * i + 1], a1);
                        a2 = fma2(f2ull(u1.x, u1.y), wreg[2 * i + 2], a2);
                        a3 = fma2(f2ull(u1.z, u1.w), wreg[2 * i + 3], a3);
                        a0 = fma2(f2ull(u2.x, u2.y), wreg[2 * i + 4], a0);
                        a1 = fma2(f2ull(u2.z, u2.w), wreg[2 * i + 5], a1);
                        a2 = fma2(f2ull(u3.x, u3.y), wreg[2 * i + 6], a2);
                        a3 = fma2(f2ull(u3.z, u3.w), wreg[2 * i + 7], a3);
                    }
                    ull u = add2(add2(a0, a1), add2(a2, a3));
                    float lo, hi;
                    ull2f(u, lo, hi);
                    hv = tanh_fast((lo + hi) + pre);
                    hbufs[ch][b][k][out] = hv;          // STS.32, stride-1
                    named_bar(1 + ch);                   // 64-thread barrier
                    prow = (const float4*)hbufs[ch][b][k];
                }
            }
        } else if (is_pre) {
            if (p < NCHUNK) {
                cp_wait_all();                           // x chunk p ready
                if (p + 1 < NCHUNK) {                    // stream chunk p+1
                    const float4* src = (const float4*)(xg + (size_t)(p + 1) * (CHUNK * IDIM));
                    uint32_t dst = smem_u32(&xbuf[ch][(p + 1) & 1][0]);
#pragma unroll
                    for (int j = 0; j < 4; j++)
                        cp_async16(dst + (uint32_t)(lane + 32 * j) * 16, src + lane + 32 * j);
                    cp_commit();
                }
                const float4* xb = xbuf[ch][p & 1];
                float* pd = &psm[ch][p & 1][0][0];
#pragma unroll 2
                for (int k = 0; k < CHUNK; k++) {
                    float4 u0 = xb[k * 8 + 0], u1 = xb[k * 8 + 1];
                    float4 u2 = xb[k * 8 + 2], u3 = xb[k * 8 + 3];
                    float4 u4 = xb[k * 8 + 4], u5 = xb[k * 8 + 5];
                    float4 u6 = xb[k * 8 + 6], u7 = xb[k * 8 + 7];
                    ull q0 = f2ull(u0.x, u0.y), q1 = f2ull(u0.z, u0.w);
                    ull q2 = f2ull(u1.x, u1.y), q3 = f2ull(u1.z, u1.w);
                    ull q4 = f2ull(u2.x, u2.y), q5 = f2ull(u2.z, u2.w);
                    ull q6 = f2ull(u3.x, u3.y), q7 = f2ull(u3.z, u3.w);
                    ull q8 = f2ull(u4.x, u4.y), q9 = f2ull(u4.z, u4.w);
                    ull qa = f2ull(u5.x, u5.y), qb = f2ull(u5.z, u5.w);
                    ull qc = f2ull(u6.x, u6.y), qd = f2ull(u6.z, u6.w);
                    ull qe = f2ull(u7.x, u7.y), qf = f2ull(u7.z, u7.w);
                    ull aA0 = 0, aA1 = 0, aB0 = 0, aB1 = 0;
                    aA0 = fma2(q0, wreg[0],  aA0); aB0 = fma2(q0, wreg[16], aB0);
                    aA1 = fma2(q1, wreg[1],  aA1); aB1 = fma2(q1, wreg[17], aB1);
                    aA0 = fma2(q2, wreg[2],  aA0); aB0 = fma2(q2, wreg[18], aB0);
                    aA1 = fma2(q3, wreg[3],  aA1); aB1 = fma2(q3, wreg[19], aB1);
                    aA0 = fma2(q4, wreg[4],  aA0); aB0 = fma2(q4, wreg[20], aB0);
                    aA1 = fma2(q5, wreg[5],  aA1); aB1 = fma2(q5, wreg[21], aB1);
                    aA0 = fma2(q6, wreg[6],  aA0); aB0 = fma2(q6, wreg[22], aB0);
                    aA1 = fma2(q7, wreg[7],  aA1); aB1 = fma2(q7, wreg[23], aB1);
                    aA0 = fma2(q8, wreg[8],  aA0); aB0 = fma2(q8, wreg[24], aB0);
                    aA1 = fma2(q9, wreg[9],  aA1); aB1 = fma2(q9, wreg[25], aB1);
                    aA0 = fma2(qa, wreg[10], aA0); aB0 = fma2(qa, wreg[26], aB0);
                    aA1 = fma2(qb, wreg[11], aA1); aB1 = fma2(qb, wreg[27], aB1);
                    aA0 = fma2(qc, wreg[12], aA0); aB0 = fma2(qc, wreg[28], aB0);
                    aA1 = fma2(qd, wreg[13], aA1); aB1 = fma2(qd, wreg[29], aB1);
                    aA0 = fma2(qe, wreg[14], aA0); aB0 = fma2(qe, wreg[30], aB0);
                    aA1 = fma2(qf, wreg[15], aA1); aB1 = fma2(qf, wreg[31], aB1);
                    ull uA = add2(aA0, aA1), uB = add2(aB0, aB1);
                    float la, ha, lb, hb;
                    ull2f(uA, la, ha); ull2f(uB, lb, hb);
                    ((float2*)(pd + k * HDIM))[lane] =
                        make_float2((la + ha) + biasA, (lb + hb) + biasB);
                }
            }
        } else {
            if (p >= 2) {
                const int q  = p - 2;
                const int bq = q & 1;
                // hidden write-back (coalesced STG.128)
                const float4* hsrc = (const float4*)hbufs[ch][bq];
                float4* hdst = (float4*)(hg + (size_t)q * (CHUNK * HDIM));
#pragma unroll
                for (int j = 0; j < 8; j++)
                    hdst[lane + 32 * j] = hsrc[lane + 32 * j];
                // fc: obs[row][lane]
                float* od = og + (size_t)q * (CHUNK * ODIM);
#pragma unroll 2
                for (int rr = 0; rr < CHUNK; rr++) {
                    const float4* hv4 = (const float4*)hbufs[ch][bq][rr];
                    ull a0 = 0, a1 = 0, a2 = 0, a3 = 0;
#pragma unroll
                    for (int i = 0; i < 16; i += 4) {
                        float4 u0 = hv4[i],     u1 = hv4[i + 1];
                        float4 u2 = hv4[i + 2], u3 = hv4[i + 3];
                        a0 = fma2(f2ull(u0.x, u0.y), wreg[2 * i],     a0);
                        a1 = fma2(f2ull(u0.z, u0.w), wreg[2 * i + 1], a1);
                        a2 = fma2(f2ull(u1.x, u1.y), wreg[2 * i + 2], a2);
                        a3 = fma2(f2ull(u1.z, u1.w), wreg[2 * i + 3], a3);
                        a0 = fma2(f2ull(u2.x, u2.y), wreg[2 * i + 4], a0);
                        a1 = fma2(f2ull(u2.z, u2.w), wreg[2 * i + 5], a1);
                        a2 = fma2(f2ull(u3.x, u3.y), wreg[2 * i + 6], a2);
                        a3 = fma2(f2ull(u3.z, u3.w), wreg[2 * i + 7], a3);
                    }
                    ull u = add2(add2(a0, a1), add2(a2, a3));
                    float lo, hi;
                    ull2f(u, lo, hi);
                    od[rr * ODIM + lane] = (lo + hi) + bfc;
                }
            }
        }
        __syncthreads();
    }

    if (is_rec) h_last[chain * HDIM + out] = hv;
}

// ---------------------------------------------------------------------------
// Launch. d_out layout: [observations | hidden | h_last], fp32.
// ---------------------------------------------------------------------------
extern "C" void kernel_launch(void* const* d_in, const int* in_sizes, int n_in,
                              void* d_out, int out_size) {
    const float* x    = (const float*)d_in[0];
    const float* W_ih = (const float*)d_in[1];
    const float* b_ih = (const float*)d_in[2];
    const float* W_hh = (const float*)d_in[3];
    const float* b_hh = (const float*)d_in[4];
    const float* W_fc = (const float*)d_in[5];
    const float* b_fc = (const float*)d_in[6];

    float* obs    = (float*)d_out;
    float* hid    = obs + OBS_N;
    float* h_last = hid + HID_N;

    fused_rnn_kernel<<<NCHAIN / 2, 256>>>(x, W_ih, b_ih, W_hh, b_hh, W_fc, b_fc,
                                          obs, hid, h_last);
}